// round 14
// baseline (speedup 1.0000x reference)
#include <cuda_runtime.h>
#include <cuda_fp16.h>
#include <cstdint>

#define N_NODES_MAX 100000
#define HID 64
#define CAP 128   // per-node neighbor bucket capacity (Poisson(16) => ample)

// Scratch (device globals; no runtime allocation allowed)
__device__ __align__(16) __half g_hsA[N_NODES_MAX * HID];
__device__ __align__(16) __half g_hsB[N_NODES_MAX * HID];
__device__ int   g_cursor[N_NODES_MAX];     // per-node fill cursor == in-degree
__device__ int   g_csr[N_NODES_MAX * CAP];  // bucketed CSR (src by dst)
__device__ int   g_is_i32;                  // dtype detection flag

// ---------------------------------------------------------------------------
// packed fp32 helpers (FFMA2)
// ---------------------------------------------------------------------------
__device__ __forceinline__ void fma2(unsigned long long& acc,
                                     unsigned long long x,
                                     unsigned long long w) {
    asm("fma.rn.f32x2 %0, %1, %2, %0;" : "+l"(acc) : "l"(x), "l"(w));
}

__device__ __forceinline__ int edge_at(const void* ei, long long idx, int is32) {
    return is32 ? ((const int*)ei)[idx] : (int)((const long long*)ei)[idx];
}

// ---------------------------------------------------------------------------
// fused: zero cursor everywhere; block 0 also detects edge dtype
// ---------------------------------------------------------------------------
__global__ void k_detect_zero(const unsigned long long* __restrict__ ei,
                              long long nwords, unsigned long long limit,
                              int* __restrict__ flag, int* __restrict__ cursor,
                              int N)
{
    int i = blockIdx.x * blockDim.x + threadIdx.x;
    if (i < N) cursor[i] = 0;
    if (blockIdx.x == 0) {
        __shared__ int found;
        if (threadIdx.x == 0) found = 0;
        __syncthreads();
        for (long long t = threadIdx.x; t < nwords; t += blockDim.x) {
            if (ei[t] >= limit) { found = 1; break; }
        }
        __syncthreads();
        if (threadIdx.x == 0) *flag = found;  // 1 => int32, 0 => int64
    }
}

// single-pass bucket scatter, 4 edges per thread for MLP
__global__ void k_scatter(const void* __restrict__ ei,
                          int* __restrict__ cursor, int* __restrict__ csr,
                          long long E, const int* __restrict__ flag)
{
    long long base = ((long long)blockIdx.x * blockDim.x + threadIdx.x) * 4;
    if (base >= E) return;
    int is32 = *flag;
    int srcs[4], dsts[4];
    int n = (E - base < 4) ? (int)(E - base) : 4;
    #pragma unroll
    for (int i = 0; i < 4; ++i) {
        if (i < n) {
            srcs[i] = edge_at(ei, base + i, is32);
            dsts[i] = edge_at(ei, E + base + i, is32);
        }
    }
    #pragma unroll
    for (int i = 0; i < 4; ++i) {
        if (i < n) {
            int slot = atomicAdd(&cursor[dsts[i]], 1);
            if (slot < CAP) csr[(long long)dsts[i] * CAP + slot] = srcs[i];
        }
    }
}

// ---------------------------------------------------------------------------
// GEMM layer 1: hsA = fp16( (X[N,128] @ W1[128,64]) * rsqrt(deg+1) )
// 256 threads/block, 128x64 tile, 8 rows x 4 cols per thread, f32x2 accum,
// register-prefetch pipeline (measured 42us).
// ---------------------------------------------------------------------------
__global__ void __launch_bounds__(256, 2) k_gemm1(
    const float* __restrict__ X, const float* __restrict__ W,
    const int* __restrict__ cursor, uint2* __restrict__ hs16, int N)
{
    constexpr int K = 128;
    constexpr int KC = 32;
    constexpr int NCH = K / KC;
    constexpr int XSTR = 132;
    __shared__ __align__(16) float sX[KC * XSTR];
    __shared__ __align__(16) float sW[KC * 64];

    const int tid = threadIdx.x;
    const int r = tid >> 4;
    const int c = tid & 15;
    const int row0 = blockIdx.x * 128;

    int w_kk[2], w_cq[2];
    int x_row[4], x_kq[4], x_grow[4];
    #pragma unroll
    for (int i = 0; i < 2; ++i) {
        int idx = tid + i * 256;
        w_kk[i] = idx >> 4;
        w_cq[i] = idx & 15;
    }
    #pragma unroll
    for (int i = 0; i < 4; ++i) {
        int idx = tid + i * 256;
        x_row[i] = idx >> 3;
        x_kq[i]  = idx & 7;
        x_grow[i] = row0 + x_row[i];
    }

    const float4* X4 = (const float4*)X;
    const float4* W4 = (const float4*)W;

    unsigned long long acc[4][4];
    #pragma unroll
    for (int i = 0; i < 4; ++i)
        #pragma unroll
        for (int j = 0; j < 4; ++j) acc[i][j] = 0ull;

    float4 wreg[2], xreg[4];
    #pragma unroll
    for (int i = 0; i < 2; ++i)
        wreg[i] = W4[(long long)w_kk[i] * 16 + w_cq[i]];
    #pragma unroll
    for (int i = 0; i < 4; ++i) {
        xreg[i] = make_float4(0.f, 0.f, 0.f, 0.f);
        if (x_grow[i] < N) xreg[i] = X4[(long long)x_grow[i] * (K / 4) + x_kq[i]];
    }

    #pragma unroll
    for (int ch = 0; ch < NCH; ++ch) {
        #pragma unroll
        for (int i = 0; i < 2; ++i)
            *(float4*)&sW[w_kk[i] * 64 + w_cq[i] * 4] = wreg[i];
        #pragma unroll
        for (int i = 0; i < 4; ++i) {
            sX[(x_kq[i] * 4 + 0) * XSTR + x_row[i]] = xreg[i].x;
            sX[(x_kq[i] * 4 + 1) * XSTR + x_row[i]] = xreg[i].y;
            sX[(x_kq[i] * 4 + 2) * XSTR + x_row[i]] = xreg[i].z;
            sX[(x_kq[i] * 4 + 3) * XSTR + x_row[i]] = xreg[i].w;
        }
        __syncthreads();

        if (ch + 1 < NCH) {
            int kc0 = (ch + 1) * KC;
            #pragma unroll
            for (int i = 0; i < 2; ++i)
                wreg[i] = W4[(long long)(kc0 + w_kk[i]) * 16 + w_cq[i]];
            #pragma unroll
            for (int i = 0; i < 4; ++i) {
                xreg[i] = make_float4(0.f, 0.f, 0.f, 0.f);
                if (x_grow[i] < N)
                    xreg[i] = X4[(long long)x_grow[i] * (K / 4) + kc0 / 4 + x_kq[i]];
            }
        }

        #pragma unroll
        for (int k = 0; k < KC; ++k) {
            float4 xa = *(const float4*)&sX[k * XSTR + r * 8 + 0];
            float4 xb = *(const float4*)&sX[k * XSTR + r * 8 + 4];
            float4 w  = *(const float4*)&sW[k * 64 + c * 4];
            unsigned long long xp[4];
            xp[0] = *(unsigned long long*)&xa.x;
            xp[1] = *(unsigned long long*)&xa.z;
            xp[2] = *(unsigned long long*)&xb.x;
            xp[3] = *(unsigned long long*)&xb.z;
            float wv[4] = {w.x, w.y, w.z, w.w};
            #pragma unroll
            for (int j = 0; j < 4; ++j) {
                unsigned long long wd;
                asm("mov.b64 %0, {%1, %1};" : "=l"(wd) : "f"(wv[j]));
                #pragma unroll
                for (int rp = 0; rp < 4; ++rp) fma2(acc[rp][j], xp[rp], wd);
            }
        }
        __syncthreads();
    }

    #pragma unroll
    for (int rp = 0; rp < 4; ++rp) {
        #pragma unroll
        for (int half = 0; half < 2; ++half) {
            int row = row0 + r * 8 + rp * 2 + half;
            if (row < N) {
                float d = rsqrtf((float)(cursor[row] + 1));
                float o0 = ((float*)&acc[rp][0])[half] * d;
                float o1 = ((float*)&acc[rp][1])[half] * d;
                float o2 = ((float*)&acc[rp][2])[half] * d;
                float o3 = ((float*)&acc[rp][3])[half] * d;
                __half2 p0 = __floats2half2_rn(o0, o1);
                __half2 p1 = __floats2half2_rn(o2, o3);
                uint2 u;
                u.x = *(unsigned*)&p0;
                u.y = *(unsigned*)&p1;
                hs16[(long long)row * 16 + c] = u;
            }
        }
    }
}

// ---------------------------------------------------------------------------
// fp16 gather helper
// ---------------------------------------------------------------------------
__device__ __forceinline__ void acc_u4(float2* a, uint4 v) {
    float2 f0 = __half22float2(*(__half2*)&v.x);
    float2 f1 = __half22float2(*(__half2*)&v.y);
    float2 f2 = __half22float2(*(__half2*)&v.z);
    float2 f3 = __half22float2(*(__half2*)&v.w);
    a[0].x += f0.x; a[0].y += f0.y;
    a[1].x += f1.x; a[1].y += f1.y;
    a[2].x += f2.x; a[2].y += f2.y;
    a[3].x += f3.x; a[3].y += f3.y;
}

// ---------------------------------------------------------------------------
// FUSED layer: feat = relu(dis*(agg hs_in) + b) computed into smem (transposed
// GEMM staging), then hs_out = fp16( (feat @ W[64,64]) * dis ).
// 256 threads, 128 nodes/block. Phase A: 4 chunks x (32 nodes x 8 lanes).
// ---------------------------------------------------------------------------
__global__ void __launch_bounds__(256, 2) k_fused(
    const uint4* __restrict__ hs_in, const int* __restrict__ cursor,
    const int* __restrict__ csr, const float* __restrict__ b,
    const float* __restrict__ W, uint2* __restrict__ hs_out, int N)
{
    constexpr int XSTR = 132;
    __shared__ __align__(16) float sX[64 * XSTR];  // feat^T [k][node] 33.8KB
    __shared__ __align__(16) float sW[64 * 64];    // 16KB
    __shared__ float sD[128];

    const int tid = threadIdx.x;
    const int node0 = blockIdx.x * 128;

    // stage W [64,64]
    {
        const float4* W4 = (const float4*)W;
        #pragma unroll
        for (int i = 0; i < 4; ++i) {
            int idx = tid + i * 256;
            ((float4*)sW)[idx] = W4[idx];
        }
    }

    // Phase A: gather + finalize
    const int h = tid & 7;
    const int nsub = tid >> 3;             // 0..31
    float4 b0 = ((const float4*)b)[h * 2 + 0];
    float4 b1 = ((const float4*)b)[h * 2 + 1];

    #pragma unroll 1
    for (int cn = 0; cn < 4; ++cn) {
        int nl = cn * 32 + nsub;
        int node = node0 + nl;
        float2 a[4] = {{0.f,0.f},{0.f,0.f},{0.f,0.f},{0.f,0.f}};
        float d = 0.f;
        if (node < N) {
            int deg = cursor[node];
            if (deg > CAP) deg = CAP;
            d = rsqrtf((float)(deg + 1));
            acc_u4(a, hs_in[(long long)node * 8 + h]);   // self loop
            const int* nb = csr + (long long)node * CAP;
            int p = 0;
            for (; p + 7 < deg; p += 8) {
                int s[8];
                #pragma unroll
                for (int i = 0; i < 8; ++i) s[i] = nb[p + i];
                uint4 v[8];
                #pragma unroll
                for (int i = 0; i < 8; ++i)
                    v[i] = __ldg(&hs_in[(long long)s[i] * 8 + h]);
                #pragma unroll
                for (int i = 0; i < 8; ++i) acc_u4(a, v[i]);
            }
            for (; p + 3 < deg; p += 4) {
                uint4 v0 = __ldg(&hs_in[(long long)nb[p]     * 8 + h]);
                uint4 v1 = __ldg(&hs_in[(long long)nb[p + 1] * 8 + h]);
                uint4 v2 = __ldg(&hs_in[(long long)nb[p + 2] * 8 + h]);
                uint4 v3 = __ldg(&hs_in[(long long)nb[p + 3] * 8 + h]);
                acc_u4(a, v0); acc_u4(a, v1); acc_u4(a, v2); acc_u4(a, v3);
            }
            for (; p < deg; ++p) {
                uint4 v0 = __ldg(&hs_in[(long long)nb[p] * 8 + h]);
                acc_u4(a, v0);
            }
        }
        float f[8];
        f[0] = fmaxf(fmaf(d, a[0].x, b0.x), 0.f);
        f[1] = fmaxf(fmaf(d, a[0].y, b0.y), 0.f);
        f[2] = fmaxf(fmaf(d, a[1].x, b0.z), 0.f);
        f[3] = fmaxf(fmaf(d, a[1].y, b0.w), 0.f);
        f[4] = fmaxf(fmaf(d, a[2].x, b1.x), 0.f);
        f[5] = fmaxf(fmaf(d, a[2].y, b1.y), 0.f);
        f[6] = fmaxf(fmaf(d, a[3].x, b1.z), 0.f);
        f[7] = fmaxf(fmaf(d, a[3].y, b1.w), 0.f);
        // transposed store into GEMM staging
        #pragma unroll
        for (int j = 0; j < 8; ++j)
            sX[(h * 8 + j) * XSTR + nl] = f[j];
        if (h == 0) sD[nl] = d;
    }
    __syncthreads();

    // Phase B: GEMM 128x64 @ 64x64 from smem
    const int r = tid >> 4;
    const int c = tid & 15;
    unsigned long long acc[4][4];
    #pragma unroll
    for (int i = 0; i < 4; ++i)
        #pragma unroll
        for (int j = 0; j < 4; ++j) acc[i][j] = 0ull;

    #pragma unroll
    for (int k = 0; k < 64; ++k) {
        float4 xa = *(const float4*)&sX[k * XSTR + r * 8 + 0];
        float4 xb = *(const float4*)&sX[k * XSTR + r * 8 + 4];
        float4 w  = *(const float4*)&sW[k * 64 + c * 4];
        unsigned long long xp[4];
        xp[0] = *(unsigned long long*)&xa.x;
        xp[1] = *(unsigned long long*)&xa.z;
        xp[2] = *(unsigned long long*)&xb.x;
        xp[3] = *(unsigned long long*)&xb.z;
        float wv[4] = {w.x, w.y, w.z, w.w};
        #pragma unroll
        for (int j = 0; j < 4; ++j) {
            unsigned long long wd;
            asm("mov.b64 %0, {%1, %1};" : "=l"(wd) : "f"(wv[j]));
            #pragma unroll
            for (int rp = 0; rp < 4; ++rp) fma2(acc[rp][j], xp[rp], wd);
        }
    }

    // epilogue
    #pragma unroll
    for (int rp = 0; rp < 4; ++rp) {
        #pragma unroll
        for (int half = 0; half < 2; ++half) {
            int rl = r * 8 + rp * 2 + half;
            int row = node0 + rl;
            if (row < N) {
                float d = sD[rl];
                float o0 = ((float*)&acc[rp][0])[half] * d;
                float o1 = ((float*)&acc[rp][1])[half] * d;
                float o2 = ((float*)&acc[rp][2])[half] * d;
                float o3 = ((float*)&acc[rp][3])[half] * d;
                __half2 p0 = __floats2half2_rn(o0, o1);
                __half2 p1 = __floats2half2_rn(o2, o3);
                uint2 u;
                u.x = *(unsigned*)&p0;
                u.y = *(unsigned*)&p1;
                hs_out[(long long)row * 16 + c] = u;
            }
        }
    }
}

// ---------------------------------------------------------------------------
// Final aggregation + readout: out[i] = (relu(dis*(agg hs)+b)) . Wout + bout
// ---------------------------------------------------------------------------
__global__ void __launch_bounds__(256) k_agg_readout(
    const uint4* __restrict__ hs, const int* __restrict__ cursor,
    const int* __restrict__ csr, const float* __restrict__ b,
    float* __restrict__ out, const float* __restrict__ Wout,
    const float* __restrict__ bout, int N)
{
    int node = blockIdx.x * 32 + (threadIdx.x >> 3);
    int h = threadIdx.x & 7;
    if (node >= N) return;

    float2 a[4] = {{0.f,0.f},{0.f,0.f},{0.f,0.f},{0.f,0.f}};
    acc_u4(a, hs[(long long)node * 8 + h]);

    int deg = cursor[node];
    if (deg > CAP) deg = CAP;
    float d = rsqrtf((float)(deg + 1));
    const int* nb = csr + (long long)node * CAP;

    int p = 0;
    for (; p + 7 < deg; p += 8) {
        int s[8];
        #pragma unroll
        for (int i = 0; i < 8; ++i) s[i] = nb[p + i];
        uint4 v[8];
        #pragma unroll
        for (int i = 0; i < 8; ++i) v[i] = __ldg(&hs[(long long)s[i] * 8 + h]);
        #pragma unroll
        for (int i = 0; i < 8; ++i) acc_u4(a, v[i]);
    }
    for (; p + 3 < deg; p += 4) {
        uint4 v0 = __ldg(&hs[(long long)nb[p]     * 8 + h]);
        uint4 v1 = __ldg(&hs[(long long)nb[p + 1] * 8 + h]);
        uint4 v2 = __ldg(&hs[(long long)nb[p + 2] * 8 + h]);
        uint4 v3 = __ldg(&hs[(long long)nb[p + 3] * 8 + h]);
        acc_u4(a, v0); acc_u4(a, v1); acc_u4(a, v2); acc_u4(a, v3);
    }
    for (; p < deg; ++p) {
        uint4 v0 = __ldg(&hs[(long long)nb[p] * 8 + h]);
        acc_u4(a, v0);
    }

    float4 b0 = ((const float4*)b)[h * 2 + 0];
    float4 b1 = ((const float4*)b)[h * 2 + 1];
    float f[8];
    f[0] = fmaxf(fmaf(d, a[0].x, b0.x), 0.f);
    f[1] = fmaxf(fmaf(d, a[0].y, b0.y), 0.f);
    f[2] = fmaxf(fmaf(d, a[1].x, b0.z), 0.f);
    f[3] = fmaxf(fmaf(d, a[1].y, b0.w), 0.f);
    f[4] = fmaxf(fmaf(d, a[2].x, b1.x), 0.f);
    f[5] = fmaxf(fmaf(d, a[2].y, b1.y), 0.f);
    f[6] = fmaxf(fmaf(d, a[3].x, b1.z), 0.f);
    f[7] = fmaxf(fmaf(d, a[3].y, b1.w), 0.f);

    float4 w0 = ((const float4*)Wout)[h * 2 + 0];
    float4 w1 = ((const float4*)Wout)[h * 2 + 1];
    float s = f[0]*w0.x + f[1]*w0.y + f[2]*w0.z + f[3]*w0.w
            + f[4]*w1.x + f[5]*w1.y + f[6]*w1.z + f[7]*w1.w;
    #pragma unroll
    for (int o = 4; o; o >>= 1) s += __shfl_xor_sync(0xFFFFFFFFu, s, o);
    if (h == 0) out[node] = s + bout[0];
}

// ---------------------------------------------------------------------------
extern "C" void kernel_launch(void* const* d_in, const int* in_sizes, int n_in,
                              void* d_out, int out_size)
{
    const float* x    = (const float*)d_in[0];
    const void*  eraw = d_in[1];
    const float* W1   = (const float*)d_in[2];
    const float* b1   = (const float*)d_in[3];
    const float* W2   = (const float*)d_in[4];
    const float* b2   = (const float*)d_in[5];
    const float* W3   = (const float*)d_in[6];
    const float* b3   = (const float*)d_in[7];
    const float* Wout = (const float*)d_in[8];
    const float* bout = (const float*)d_in[9];
    float*       out  = (float*)d_out;

    const int N = in_sizes[0] / 128;
    const long long E = in_sizes[1] / 2;

    void *hsAv, *hsBv;
    int *flag, *cursor, *csr;
    cudaGetSymbolAddress(&hsAv,            g_hsA);
    cudaGetSymbolAddress(&hsBv,            g_hsB);
    cudaGetSymbolAddress((void**)&flag,    g_is_i32);
    cudaGetSymbolAddress((void**)&cursor,  g_cursor);
    cudaGetSymbolAddress((void**)&csr,     g_csr);

    const int TB = 256;
    long long nwords = E < 4096 ? E : 4096;

    const int gemm_blocks  = (N + 127) / 128;
    const int fused_blocks = (N + 127) / 128;
    const int aggr_blocks  = (N + 31) / 32;
    const int edge4_blocks = (int)((E + 4LL * TB - 1) / (4LL * TB));

    // 0: zero cursor + dtype detect
    k_detect_zero<<<(N + TB - 1) / TB, TB>>>(
        (const unsigned long long*)eraw, nwords, (unsigned long long)N,
        flag, cursor, N);
    // 1: bucket scatter
    k_scatter<<<edge4_blocks, TB>>>(eraw, cursor, csr, E, flag);
    // 2: GEMM layer 1 -> hsA
    k_gemm1<<<gemm_blocks, 256>>>(x, W1, cursor, (uint2*)hsAv, N);
    // 3: fused agg1 + gemm2 -> hsB   (profiled launch)
    k_fused<<<fused_blocks, 256>>>((const uint4*)hsAv, cursor, csr, b1, W2,
                                   (uint2*)hsBv, N);
    // 4: fused agg2 + gemm3 -> hsA
    k_fused<<<fused_blocks, 256>>>((const uint4*)hsBv, cursor, csr, b2, W3,
                                   (uint2*)hsAv, N);
    // 5: final agg + readout
    k_agg_readout<<<aggr_blocks, TB>>>((const uint4*)hsAv, cursor, csr, b3,
                                       out, Wout, bout, N);
}

// round 15
// speedup vs baseline: 1.1039x; 1.1039x over previous
#include <cuda_runtime.h>
#include <cuda_fp16.h>
#include <cstdint>

#define N_NODES_MAX 100000
#define HID 64
#define CAP 128   // per-node neighbor bucket capacity (Poisson(16) => ample)

// Scratch (device globals; no runtime allocation allowed)
__device__ __align__(16) __half g_hsA[N_NODES_MAX * HID];   // hs (gemm out)
__device__ __align__(16) __half g_featB[N_NODES_MAX * HID]; // feat fp16 (agg out)
__device__ int   g_cursor[N_NODES_MAX];     // per-node fill cursor == in-degree
__device__ int   g_csr[N_NODES_MAX * CAP];  // bucketed CSR (src by dst)
__device__ int   g_is_i32;                  // dtype detection flag

// ---------------------------------------------------------------------------
// packed fp32 helpers (FFMA2)
// ---------------------------------------------------------------------------
__device__ __forceinline__ void fma2(unsigned long long& acc,
                                     unsigned long long x,
                                     unsigned long long w) {
    asm("fma.rn.f32x2 %0, %1, %2, %0;" : "+l"(acc) : "l"(x), "l"(w));
}

__device__ __forceinline__ int edge_at(const void* ei, long long idx, int is32) {
    return is32 ? ((const int*)ei)[idx] : (int)((const long long*)ei)[idx];
}

// ---------------------------------------------------------------------------
// fused: zero cursor everywhere; block 0 also detects edge dtype
// ---------------------------------------------------------------------------
__global__ void k_detect_zero(const unsigned long long* __restrict__ ei,
                              long long nwords, unsigned long long limit,
                              int* __restrict__ flag, int* __restrict__ cursor,
                              int N)
{
    int i = blockIdx.x * blockDim.x + threadIdx.x;
    if (i < N) cursor[i] = 0;
    if (blockIdx.x == 0) {
        __shared__ int found;
        if (threadIdx.x == 0) found = 0;
        __syncthreads();
        for (long long t = threadIdx.x; t < nwords; t += blockDim.x) {
            if (ei[t] >= limit) { found = 1; break; }
        }
        __syncthreads();
        if (threadIdx.x == 0) *flag = found;  // 1 => int32, 0 => int64
    }
}

// single-pass bucket scatter, 4 edges per thread for MLP
__global__ void k_scatter(const void* __restrict__ ei,
                          int* __restrict__ cursor, int* __restrict__ csr,
                          long long E, const int* __restrict__ flag)
{
    long long base = ((long long)blockIdx.x * blockDim.x + threadIdx.x) * 4;
    if (base >= E) return;
    int is32 = *flag;
    int srcs[4], dsts[4];
    int n = (E - base < 4) ? (int)(E - base) : 4;
    #pragma unroll
    for (int i = 0; i < 4; ++i) {
        if (i < n) {
            srcs[i] = edge_at(ei, base + i, is32);
            dsts[i] = edge_at(ei, E + base + i, is32);
        }
    }
    #pragma unroll
    for (int i = 0; i < 4; ++i) {
        if (i < n) {
            int slot = atomicAdd(&cursor[dsts[i]], 1);
            if (slot < CAP) csr[(long long)dsts[i] * CAP + slot] = srcs[i];
        }
    }
}

// ---------------------------------------------------------------------------
// GEMM layer 1: hsA = fp16( (X[N,128] @ W1[128,64]) * rsqrt(deg+1) )
// (proven R13/R14 kernel: 256 thr, 128x64 tile, 8x4/thread, f32x2,
//  register-prefetch pipeline)
// ---------------------------------------------------------------------------
__global__ void __launch_bounds__(256, 2) k_gemm1(
    const float* __restrict__ X, const float* __restrict__ W,
    const int* __restrict__ cursor, uint2* __restrict__ hs16, int N)
{
    constexpr int K = 128;
    constexpr int KC = 32;
    constexpr int NCH = K / KC;
    constexpr int XSTR = 132;
    __shared__ __align__(16) float sX[KC * XSTR];
    __shared__ __align__(16) float sW[KC * 64];

    const int tid = threadIdx.x;
    const int r = tid >> 4;
    const int c = tid & 15;
    const int row0 = blockIdx.x * 128;

    int w_kk[2], w_cq[2];
    int x_row[4], x_kq[4], x_grow[4];
    #pragma unroll
    for (int i = 0; i < 2; ++i) {
        int idx = tid + i * 256;
        w_kk[i] = idx >> 4;
        w_cq[i] = idx & 15;
    }
    #pragma unroll
    for (int i = 0; i < 4; ++i) {
        int idx = tid + i * 256;
        x_row[i] = idx >> 3;
        x_kq[i]  = idx & 7;
        x_grow[i] = row0 + x_row[i];
    }

    const float4* X4 = (const float4*)X;
    const float4* W4 = (const float4*)W;

    unsigned long long acc[4][4];
    #pragma unroll
    for (int i = 0; i < 4; ++i)
        #pragma unroll
        for (int j = 0; j < 4; ++j) acc[i][j] = 0ull;

    float4 wreg[2], xreg[4];
    #pragma unroll
    for (int i = 0; i < 2; ++i)
        wreg[i] = W4[(long long)w_kk[i] * 16 + w_cq[i]];
    #pragma unroll
    for (int i = 0; i < 4; ++i) {
        xreg[i] = make_float4(0.f, 0.f, 0.f, 0.f);
        if (x_grow[i] < N) xreg[i] = X4[(long long)x_grow[i] * (K / 4) + x_kq[i]];
    }

    #pragma unroll
    for (int ch = 0; ch < NCH; ++ch) {
        #pragma unroll
        for (int i = 0; i < 2; ++i)
            *(float4*)&sW[w_kk[i] * 64 + w_cq[i] * 4] = wreg[i];
        #pragma unroll
        for (int i = 0; i < 4; ++i) {
            sX[(x_kq[i] * 4 + 0) * XSTR + x_row[i]] = xreg[i].x;
            sX[(x_kq[i] * 4 + 1) * XSTR + x_row[i]] = xreg[i].y;
            sX[(x_kq[i] * 4 + 2) * XSTR + x_row[i]] = xreg[i].z;
            sX[(x_kq[i] * 4 + 3) * XSTR + x_row[i]] = xreg[i].w;
        }
        __syncthreads();

        if (ch + 1 < NCH) {
            int kc0 = (ch + 1) * KC;
            #pragma unroll
            for (int i = 0; i < 2; ++i)
                wreg[i] = W4[(long long)(kc0 + w_kk[i]) * 16 + w_cq[i]];
            #pragma unroll
            for (int i = 0; i < 4; ++i) {
                xreg[i] = make_float4(0.f, 0.f, 0.f, 0.f);
                if (x_grow[i] < N)
                    xreg[i] = X4[(long long)x_grow[i] * (K / 4) + kc0 / 4 + x_kq[i]];
            }
        }

        #pragma unroll
        for (int k = 0; k < KC; ++k) {
            float4 xa = *(const float4*)&sX[k * XSTR + r * 8 + 0];
            float4 xb = *(const float4*)&sX[k * XSTR + r * 8 + 4];
            float4 w  = *(const float4*)&sW[k * 64 + c * 4];
            unsigned long long xp[4];
            xp[0] = *(unsigned long long*)&xa.x;
            xp[1] = *(unsigned long long*)&xa.z;
            xp[2] = *(unsigned long long*)&xb.x;
            xp[3] = *(unsigned long long*)&xb.z;
            float wv[4] = {w.x, w.y, w.z, w.w};
            #pragma unroll
            for (int j = 0; j < 4; ++j) {
                unsigned long long wd;
                asm("mov.b64 %0, {%1, %1};" : "=l"(wd) : "f"(wv[j]));
                #pragma unroll
                for (int rp = 0; rp < 4; ++rp) fma2(acc[rp][j], xp[rp], wd);
            }
        }
        __syncthreads();
    }

    #pragma unroll
    for (int rp = 0; rp < 4; ++rp) {
        #pragma unroll
        for (int half = 0; half < 2; ++half) {
            int row = row0 + r * 8 + rp * 2 + half;
            if (row < N) {
                float d = rsqrtf((float)(cursor[row] + 1));
                float o0 = ((float*)&acc[rp][0])[half] * d;
                float o1 = ((float*)&acc[rp][1])[half] * d;
                float o2 = ((float*)&acc[rp][2])[half] * d;
                float o3 = ((float*)&acc[rp][3])[half] * d;
                __half2 p0 = __floats2half2_rn(o0, o1);
                __half2 p1 = __floats2half2_rn(o2, o3);
                uint2 u;
                u.x = *(unsigned*)&p0;
                u.y = *(unsigned*)&p1;
                hs16[(long long)row * 16 + c] = u;
            }
        }
    }
}

// ---------------------------------------------------------------------------
// GEMM layers 2/3: hs = fp16( (feat16[N,64] @ W[64,64]) * rsqrt(deg+1) )
// Same structure as k_gemm1 but input is fp16 (converted during staging).
// ---------------------------------------------------------------------------
__global__ void __launch_bounds__(256, 2) k_gemm16(
    const uint4* __restrict__ F16, const float* __restrict__ W,
    const int* __restrict__ cursor, uint2* __restrict__ hs16, int N)
{
    constexpr int K = 64;
    constexpr int KC = 32;
    constexpr int NCH = K / KC;            // 2
    constexpr int XSTR = 132;
    __shared__ __align__(16) float sX[KC * XSTR];
    __shared__ __align__(16) float sW[KC * 64];

    const int tid = threadIdx.x;
    const int r = tid >> 4;
    const int c = tid & 15;
    const int row0 = blockIdx.x * 128;

    int w_kk[2], w_cq[2];
    #pragma unroll
    for (int i = 0; i < 2; ++i) {
        int idx = tid + i * 256;
        w_kk[i] = idx >> 4;
        w_cq[i] = idx & 15;
    }
    // X staging: per chunk 512 uint4 items (128 rows x 4 uint4 = 32 halves)
    int x_row[2], x_q[2], x_grow[2];
    #pragma unroll
    for (int i = 0; i < 2; ++i) {
        int idx = tid + i * 256;           // [0,512)
        x_row[i] = idx >> 2;               // 0..127
        x_q[i]   = idx & 3;                // uint4 within 32-half chunk
        x_grow[i] = row0 + x_row[i];
    }

    const float4* W4 = (const float4*)W;

    unsigned long long acc[4][4];
    #pragma unroll
    for (int i = 0; i < 4; ++i)
        #pragma unroll
        for (int j = 0; j < 4; ++j) acc[i][j] = 0ull;

    float4 wreg[2];
    uint4 xreg[2];
    #pragma unroll
    for (int i = 0; i < 2; ++i)
        wreg[i] = W4[(long long)w_kk[i] * 16 + w_cq[i]];
    #pragma unroll
    for (int i = 0; i < 2; ++i) {
        xreg[i] = make_uint4(0u, 0u, 0u, 0u);
        if (x_grow[i] < N) xreg[i] = F16[(long long)x_grow[i] * 8 + x_q[i]];
    }

    #pragma unroll
    for (int ch = 0; ch < NCH; ++ch) {
        #pragma unroll
        for (int i = 0; i < 2; ++i)
            *(float4*)&sW[w_kk[i] * 64 + w_cq[i] * 4] = wreg[i];
        #pragma unroll
        for (int i = 0; i < 2; ++i) {
            const unsigned* u = &xreg[i].x;
            #pragma unroll
            for (int p = 0; p < 4; ++p) {
                float2 f = __half22float2(*(const __half2*)&u[p]);
                sX[(x_q[i] * 8 + p * 2 + 0) * XSTR + x_row[i]] = f.x;
                sX[(x_q[i] * 8 + p * 2 + 1) * XSTR + x_row[i]] = f.y;
            }
        }
        __syncthreads();

        if (ch + 1 < NCH) {
            int kc0 = (ch + 1) * KC;
            #pragma unroll
            for (int i = 0; i < 2; ++i)
                wreg[i] = W4[(long long)(kc0 + w_kk[i]) * 16 + w_cq[i]];
            #pragma unroll
            for (int i = 0; i < 2; ++i) {
                xreg[i] = make_uint4(0u, 0u, 0u, 0u);
                if (x_grow[i] < N)
                    xreg[i] = F16[(long long)x_grow[i] * 8 + kc0 / 8 + x_q[i]];
            }
        }

        #pragma unroll
        for (int k = 0; k < KC; ++k) {
            float4 xa = *(const float4*)&sX[k * XSTR + r * 8 + 0];
            float4 xb = *(const float4*)&sX[k * XSTR + r * 8 + 4];
            float4 w  = *(const float4*)&sW[k * 64 + c * 4];
            unsigned long long xp[4];
            xp[0] = *(unsigned long long*)&xa.x;
            xp[1] = *(unsigned long long*)&xa.z;
            xp[2] = *(unsigned long long*)&xb.x;
            xp[3] = *(unsigned long long*)&xb.z;
            float wv[4] = {w.x, w.y, w.z, w.w};
            #pragma unroll
            for (int j = 0; j < 4; ++j) {
                unsigned long long wd;
                asm("mov.b64 %0, {%1, %1};" : "=l"(wd) : "f"(wv[j]));
                #pragma unroll
                for (int rp = 0; rp < 4; ++rp) fma2(acc[rp][j], xp[rp], wd);
            }
        }
        __syncthreads();
    }

    #pragma unroll
    for (int rp = 0; rp < 4; ++rp) {
        #pragma unroll
        for (int half = 0; half < 2; ++half) {
            int row = row0 + r * 8 + rp * 2 + half;
            if (row < N) {
                float d = rsqrtf((float)(cursor[row] + 1));
                float o0 = ((float*)&acc[rp][0])[half] * d;
                float o1 = ((float*)&acc[rp][1])[half] * d;
                float o2 = ((float*)&acc[rp][2])[half] * d;
                float o3 = ((float*)&acc[rp][3])[half] * d;
                __half2 p0 = __floats2half2_rn(o0, o1);
                __half2 p1 = __floats2half2_rn(o2, o3);
                uint2 u;
                u.x = *(unsigned*)&p0;
                u.y = *(unsigned*)&p1;
                hs16[(long long)row * 16 + c] = u;
            }
        }
    }
}

// ---------------------------------------------------------------------------
// fp16 gather helper
// ---------------------------------------------------------------------------
__device__ __forceinline__ void acc_u4(float2* a, uint4 v) {
    float2 f0 = __half22float2(*(__half2*)&v.x);
    float2 f1 = __half22float2(*(__half2*)&v.y);
    float2 f2 = __half22float2(*(__half2*)&v.z);
    float2 f3 = __half22float2(*(__half2*)&v.w);
    a[0].x += f0.x; a[0].y += f0.y;
    a[1].x += f1.x; a[1].y += f1.y;
    a[2].x += f2.x; a[2].y += f2.y;
    a[3].x += f3.x; a[3].y += f3.y;
}

// core gather: returns f[8] finalized (relu(d*agg + b)) for lane h of node
__device__ __forceinline__ void gather_node(
    const uint4* __restrict__ hs, const int* __restrict__ cursor,
    const int* __restrict__ csr, const float* __restrict__ b,
    int node, int h, float* f, float& dout)
{
    float2 a[4] = {{0.f,0.f},{0.f,0.f},{0.f,0.f},{0.f,0.f}};
    acc_u4(a, hs[(long long)node * 8 + h]);   // self loop

    int deg = cursor[node];
    if (deg > CAP) deg = CAP;
    float d = rsqrtf((float)(deg + 1));
    dout = d;
    const int* nb = csr + (long long)node * CAP;

    int p = 0;
    for (; p + 7 < deg; p += 8) {
        int s[8];
        #pragma unroll
        for (int i = 0; i < 8; ++i) s[i] = nb[p + i];
        uint4 v[8];
        #pragma unroll
        for (int i = 0; i < 8; ++i) v[i] = __ldg(&hs[(long long)s[i] * 8 + h]);
        #pragma unroll
        for (int i = 0; i < 8; ++i) acc_u4(a, v[i]);
    }
    for (; p + 3 < deg; p += 4) {
        uint4 v0 = __ldg(&hs[(long long)nb[p]     * 8 + h]);
        uint4 v1 = __ldg(&hs[(long long)nb[p + 1] * 8 + h]);
        uint4 v2 = __ldg(&hs[(long long)nb[p + 2] * 8 + h]);
        uint4 v3 = __ldg(&hs[(long long)nb[p + 3] * 8 + h]);
        acc_u4(a, v0); acc_u4(a, v1); acc_u4(a, v2); acc_u4(a, v3);
    }
    for (; p < deg; ++p) {
        uint4 v0 = __ldg(&hs[(long long)nb[p] * 8 + h]);
        acc_u4(a, v0);
    }

    float4 b0 = ((const float4*)b)[h * 2 + 0];
    float4 b1 = ((const float4*)b)[h * 2 + 1];
    f[0] = fmaxf(fmaf(d, a[0].x, b0.x), 0.f);
    f[1] = fmaxf(fmaf(d, a[0].y, b0.y), 0.f);
    f[2] = fmaxf(fmaf(d, a[1].x, b0.z), 0.f);
    f[3] = fmaxf(fmaf(d, a[1].y, b0.w), 0.f);
    f[4] = fmaxf(fmaf(d, a[2].x, b1.x), 0.f);
    f[5] = fmaxf(fmaf(d, a[2].y, b1.y), 0.f);
    f[6] = fmaxf(fmaf(d, a[3].x, b1.z), 0.f);
    f[7] = fmaxf(fmaf(d, a[3].y, b1.w), 0.f);
}

// aggregation -> fp16 feat (uint4 per lane, perfectly coalesced)
__global__ void __launch_bounds__(256) k_agg_f16(
    const uint4* __restrict__ hs, const int* __restrict__ cursor,
    const int* __restrict__ csr, const float* __restrict__ b,
    uint4* __restrict__ feat16, int N)
{
    int node = blockIdx.x * 32 + (threadIdx.x >> 3);
    int h = threadIdx.x & 7;
    if (node >= N) return;
    float f[8], d;
    gather_node(hs, cursor, csr, b, node, h, f, d);
    __half2 p0 = __floats2half2_rn(f[0], f[1]);
    __half2 p1 = __floats2half2_rn(f[2], f[3]);
    __half2 p2 = __floats2half2_rn(f[4], f[5]);
    __half2 p3 = __floats2half2_rn(f[6], f[7]);
    uint4 u;
    u.x = *(unsigned*)&p0;
    u.y = *(unsigned*)&p1;
    u.z = *(unsigned*)&p2;
    u.w = *(unsigned*)&p3;
    feat16[(long long)node * 8 + h] = u;
}

// final aggregation + readout
__global__ void __launch_bounds__(256) k_agg_readout(
    const uint4* __restrict__ hs, const int* __restrict__ cursor,
    const int* __restrict__ csr, const float* __restrict__ b,
    float* __restrict__ out, const float* __restrict__ Wout,
    const float* __restrict__ bout, int N)
{
    int node = blockIdx.x * 32 + (threadIdx.x >> 3);
    int h = threadIdx.x & 7;
    if (node >= N) return;
    float f[8], d;
    gather_node(hs, cursor, csr, b, node, h, f, d);
    float4 w0 = ((const float4*)Wout)[h * 2 + 0];
    float4 w1 = ((const float4*)Wout)[h * 2 + 1];
    float s = f[0]*w0.x + f[1]*w0.y + f[2]*w0.z + f[3]*w0.w
            + f[4]*w1.x + f[5]*w1.y + f[6]*w1.z + f[7]*w1.w;
    #pragma unroll
    for (int o = 4; o; o >>= 1) s += __shfl_xor_sync(0xFFFFFFFFu, s, o);
    if (h == 0) out[node] = s + bout[0];
}

// ---------------------------------------------------------------------------
extern "C" void kernel_launch(void* const* d_in, const int* in_sizes, int n_in,
                              void* d_out, int out_size)
{
    const float* x    = (const float*)d_in[0];
    const void*  eraw = d_in[1];
    const float* W1   = (const float*)d_in[2];
    const float* b1   = (const float*)d_in[3];
    const float* W2   = (const float*)d_in[4];
    const float* b2   = (const float*)d_in[5];
    const float* W3   = (const float*)d_in[6];
    const float* b3   = (const float*)d_in[7];
    const float* Wout = (const float*)d_in[8];
    const float* bout = (const float*)d_in[9];
    float*       out  = (float*)d_out;

    const int N = in_sizes[0] / 128;
    const long long E = in_sizes[1] / 2;

    void *hsAv, *featBv;
    int *flag, *cursor, *csr;
    cudaGetSymbolAddress(&hsAv,            g_hsA);
    cudaGetSymbolAddress(&featBv,          g_featB);
    cudaGetSymbolAddress((void**)&flag,    g_is_i32);
    cudaGetSymbolAddress((void**)&cursor,  g_cursor);
    cudaGetSymbolAddress((void**)&csr,     g_csr);

    const int TB = 256;
    long long nwords = E < 4096 ? E : 4096;

    const int gemm_blocks  = (N + 127) / 128;
    const int agg_blocks   = (N + 31) / 32;
    const int edge4_blocks = (int)((E + 4LL * TB - 1) / (4LL * TB));

    // 0: zero cursor + dtype detect
    k_detect_zero<<<(N + TB - 1) / TB, TB>>>(
        (const unsigned long long*)eraw, nwords, (unsigned long long)N,
        flag, cursor, N);
    // 1: bucket scatter
    k_scatter<<<edge4_blocks, TB>>>(eraw, cursor, csr, E, flag);
    // 2: GEMM layer 1 -> hsA
    k_gemm1<<<gemm_blocks, 256>>>(x, W1, cursor, (uint2*)hsAv, N);
    // 3: agg1 -> featB (fp16)   [profiled launch]
    k_agg_f16<<<agg_blocks, TB>>>((const uint4*)hsAv, cursor, csr, b1,
                                  (uint4*)featBv, N);
    // 4: GEMM layer 2 (fp16 in) -> hsA
    k_gemm16<<<gemm_blocks, 256>>>((const uint4*)featBv, W2, cursor,
                                   (uint2*)hsAv, N);
    // 5: agg2 -> featB
    k_agg_f16<<<agg_blocks, TB>>>((const uint4*)hsAv, cursor, csr, b2,
                                  (uint4*)featBv, N);
    // 6: GEMM layer 3 (fp16 in) -> hsA
    k_gemm16<<<gemm_blocks, 256>>>((const uint4*)featBv, W3, cursor,
                                   (uint2*)hsAv, N);
    // 7: final agg + readout
    k_agg_readout<<<agg_blocks, TB>>>((const uint4*)hsAv, cursor, csr, b3,
                                      out, Wout, bout, N);
}

// round 16
// speedup vs baseline: 1.1577x; 1.0487x over previous
#include <cuda_runtime.h>
#include <cuda_fp16.h>
#include <cstdint>

#define N_NODES_MAX 100000
#define HID 64
#define CAP 128   // per-node neighbor bucket capacity (Poisson(16) => ample)

// Scratch (device globals; no runtime allocation allowed)
__device__ __align__(16) __half g_hsA[N_NODES_MAX * HID];   // hs (gemm out)
__device__ __align__(16) __half g_featB[N_NODES_MAX * HID]; // feat fp16 (agg out)
__device__ int   g_cursor[N_NODES_MAX];     // per-node fill cursor == in-degree
__device__ int   g_csr[N_NODES_MAX * CAP];  // bucketed CSR (src by dst)
__device__ int   g_is_i32;                  // dtype detection flag

// ---------------------------------------------------------------------------
// packed fp32 helpers (FFMA2)
// ---------------------------------------------------------------------------
__device__ __forceinline__ void fma2(unsigned long long& acc,
                                     unsigned long long x,
                                     unsigned long long w) {
    asm("fma.rn.f32x2 %0, %1, %2, %0;" : "+l"(acc) : "l"(x), "l"(w));
}

__device__ __forceinline__ int edge_at(const void* ei, long long idx, int is32) {
    return is32 ? ((const int*)ei)[idx] : (int)((const long long*)ei)[idx];
}

// ---------------------------------------------------------------------------
// fused: zero cursor everywhere; block 0 also detects edge dtype
// ---------------------------------------------------------------------------
__global__ void k_detect_zero(const unsigned long long* __restrict__ ei,
                              long long nwords, unsigned long long limit,
                              int* __restrict__ flag, int* __restrict__ cursor,
                              int N)
{
    int i = blockIdx.x * blockDim.x + threadIdx.x;
    if (i < N) cursor[i] = 0;
    if (blockIdx.x == 0) {
        __shared__ int found;
        if (threadIdx.x == 0) found = 0;
        __syncthreads();
        for (long long t = threadIdx.x; t < nwords; t += blockDim.x) {
            if (ei[t] >= limit) { found = 1; break; }
        }
        __syncthreads();
        if (threadIdx.x == 0) *flag = found;  // 1 => int32, 0 => int64
    }
}

// single-pass bucket scatter, 4 edges per thread for MLP
__global__ void k_scatter(const void* __restrict__ ei,
                          int* __restrict__ cursor, int* __restrict__ csr,
                          long long E, const int* __restrict__ flag)
{
    long long base = ((long long)blockIdx.x * blockDim.x + threadIdx.x) * 4;
    if (base >= E) return;
    int is32 = *flag;
    int srcs[4], dsts[4];
    int n = (E - base < 4) ? (int)(E - base) : 4;
    #pragma unroll
    for (int i = 0; i < 4; ++i) {
        if (i < n) {
            srcs[i] = edge_at(ei, base + i, is32);
            dsts[i] = edge_at(ei, E + base + i, is32);
        }
    }
    #pragma unroll
    for (int i = 0; i < 4; ++i) {
        if (i < n) {
            int slot = atomicAdd(&cursor[dsts[i]], 1);
            if (slot < CAP) csr[(long long)dsts[i] * CAP + slot] = srcs[i];
        }
    }
}

// ---------------------------------------------------------------------------
// GEMM layer 1: hsA = fp16( (X[N,128] @ W1[128,64]) * rsqrt(deg+1) )
// ---------------------------------------------------------------------------
__global__ void __launch_bounds__(256, 2) k_gemm1(
    const float* __restrict__ X, const float* __restrict__ W,
    const int* __restrict__ cursor, uint2* __restrict__ hs16, int N)
{
    constexpr int K = 128;
    constexpr int KC = 32;
    constexpr int NCH = K / KC;
    constexpr int XSTR = 132;
    __shared__ __align__(16) float sX[KC * XSTR];
    __shared__ __align__(16) float sW[KC * 64];

    const int tid = threadIdx.x;
    const int r = tid >> 4;
    const int c = tid & 15;
    const int row0 = blockIdx.x * 128;

    int w_kk[2], w_cq[2];
    int x_row[4], x_kq[4], x_grow[4];
    #pragma unroll
    for (int i = 0; i < 2; ++i) {
        int idx = tid + i * 256;
        w_kk[i] = idx >> 4;
        w_cq[i] = idx & 15;
    }
    #pragma unroll
    for (int i = 0; i < 4; ++i) {
        int idx = tid + i * 256;
        x_row[i] = idx >> 3;
        x_kq[i]  = idx & 7;
        x_grow[i] = row0 + x_row[i];
    }

    const float4* X4 = (const float4*)X;
    const float4* W4 = (const float4*)W;

    unsigned long long acc[4][4];
    #pragma unroll
    for (int i = 0; i < 4; ++i)
        #pragma unroll
        for (int j = 0; j < 4; ++j) acc[i][j] = 0ull;

    float4 wreg[2], xreg[4];
    #pragma unroll
    for (int i = 0; i < 2; ++i)
        wreg[i] = W4[(long long)w_kk[i] * 16 + w_cq[i]];
    #pragma unroll
    for (int i = 0; i < 4; ++i) {
        xreg[i] = make_float4(0.f, 0.f, 0.f, 0.f);
        if (x_grow[i] < N) xreg[i] = X4[(long long)x_grow[i] * (K / 4) + x_kq[i]];
    }

    #pragma unroll
    for (int ch = 0; ch < NCH; ++ch) {
        #pragma unroll
        for (int i = 0; i < 2; ++i)
            *(float4*)&sW[w_kk[i] * 64 + w_cq[i] * 4] = wreg[i];
        #pragma unroll
        for (int i = 0; i < 4; ++i) {
            sX[(x_kq[i] * 4 + 0) * XSTR + x_row[i]] = xreg[i].x;
            sX[(x_kq[i] * 4 + 1) * XSTR + x_row[i]] = xreg[i].y;
            sX[(x_kq[i] * 4 + 2) * XSTR + x_row[i]] = xreg[i].z;
            sX[(x_kq[i] * 4 + 3) * XSTR + x_row[i]] = xreg[i].w;
        }
        __syncthreads();

        if (ch + 1 < NCH) {
            int kc0 = (ch + 1) * KC;
            #pragma unroll
            for (int i = 0; i < 2; ++i)
                wreg[i] = W4[(long long)(kc0 + w_kk[i]) * 16 + w_cq[i]];
            #pragma unroll
            for (int i = 0; i < 4; ++i) {
                xreg[i] = make_float4(0.f, 0.f, 0.f, 0.f);
                if (x_grow[i] < N)
                    xreg[i] = X4[(long long)x_grow[i] * (K / 4) + kc0 / 4 + x_kq[i]];
            }
        }

        #pragma unroll
        for (int k = 0; k < KC; ++k) {
            float4 xa = *(const float4*)&sX[k * XSTR + r * 8 + 0];
            float4 xb = *(const float4*)&sX[k * XSTR + r * 8 + 4];
            float4 w  = *(const float4*)&sW[k * 64 + c * 4];
            unsigned long long xp[4];
            xp[0] = *(unsigned long long*)&xa.x;
            xp[1] = *(unsigned long long*)&xa.z;
            xp[2] = *(unsigned long long*)&xb.x;
            xp[3] = *(unsigned long long*)&xb.z;
            float wv[4] = {w.x, w.y, w.z, w.w};
            #pragma unroll
            for (int j = 0; j < 4; ++j) {
                unsigned long long wd;
                asm("mov.b64 %0, {%1, %1};" : "=l"(wd) : "f"(wv[j]));
                #pragma unroll
                for (int rp = 0; rp < 4; ++rp) fma2(acc[rp][j], xp[rp], wd);
            }
        }
        __syncthreads();
    }

    #pragma unroll
    for (int rp = 0; rp < 4; ++rp) {
        #pragma unroll
        for (int half = 0; half < 2; ++half) {
            int row = row0 + r * 8 + rp * 2 + half;
            if (row < N) {
                float d = rsqrtf((float)(cursor[row] + 1));
                float o0 = ((float*)&acc[rp][0])[half] * d;
                float o1 = ((float*)&acc[rp][1])[half] * d;
                float o2 = ((float*)&acc[rp][2])[half] * d;
                float o3 = ((float*)&acc[rp][3])[half] * d;
                __half2 p0 = __floats2half2_rn(o0, o1);
                __half2 p1 = __floats2half2_rn(o2, o3);
                uint2 u;
                u.x = *(unsigned*)&p0;
                u.y = *(unsigned*)&p1;
                hs16[(long long)row * 16 + c] = u;
            }
        }
    }
}

// ---------------------------------------------------------------------------
// GEMM layers 2/3: hs = fp16( (feat16[N,64] @ W[64,64]) * rsqrt(deg+1) )
// ---------------------------------------------------------------------------
__global__ void __launch_bounds__(256, 2) k_gemm16(
    const uint4* __restrict__ F16, const float* __restrict__ W,
    const int* __restrict__ cursor, uint2* __restrict__ hs16, int N)
{
    constexpr int K = 64;
    constexpr int KC = 32;
    constexpr int NCH = K / KC;            // 2
    constexpr int XSTR = 132;
    __shared__ __align__(16) float sX[KC * XSTR];
    __shared__ __align__(16) float sW[KC * 64];

    const int tid = threadIdx.x;
    const int r = tid >> 4;
    const int c = tid & 15;
    const int row0 = blockIdx.x * 128;

    int w_kk[2], w_cq[2];
    #pragma unroll
    for (int i = 0; i < 2; ++i) {
        int idx = tid + i * 256;
        w_kk[i] = idx >> 4;
        w_cq[i] = idx & 15;
    }
    int x_row[2], x_q[2], x_grow[2];
    #pragma unroll
    for (int i = 0; i < 2; ++i) {
        int idx = tid + i * 256;           // [0,512)
        x_row[i] = idx >> 2;               // 0..127
        x_q[i]   = idx & 3;                // uint4 within 32-half chunk
        x_grow[i] = row0 + x_row[i];
    }

    const float4* W4 = (const float4*)W;

    unsigned long long acc[4][4];
    #pragma unroll
    for (int i = 0; i < 4; ++i)
        #pragma unroll
        for (int j = 0; j < 4; ++j) acc[i][j] = 0ull;

    float4 wreg[2];
    uint4 xreg[2];
    #pragma unroll
    for (int i = 0; i < 2; ++i)
        wreg[i] = W4[(long long)w_kk[i] * 16 + w_cq[i]];
    #pragma unroll
    for (int i = 0; i < 2; ++i) {
        xreg[i] = make_uint4(0u, 0u, 0u, 0u);
        if (x_grow[i] < N) xreg[i] = F16[(long long)x_grow[i] * 8 + x_q[i]];
    }

    #pragma unroll
    for (int ch = 0; ch < NCH; ++ch) {
        #pragma unroll
        for (int i = 0; i < 2; ++i)
            *(float4*)&sW[w_kk[i] * 64 + w_cq[i] * 4] = wreg[i];
        #pragma unroll
        for (int i = 0; i < 2; ++i) {
            const unsigned* u = &xreg[i].x;
            #pragma unroll
            for (int p = 0; p < 4; ++p) {
                float2 f = __half22float2(*(const __half2*)&u[p]);
                sX[(x_q[i] * 8 + p * 2 + 0) * XSTR + x_row[i]] = f.x;
                sX[(x_q[i] * 8 + p * 2 + 1) * XSTR + x_row[i]] = f.y;
            }
        }
        __syncthreads();

        if (ch + 1 < NCH) {
            int kc0 = (ch + 1) * KC;
            #pragma unroll
            for (int i = 0; i < 2; ++i)
                wreg[i] = W4[(long long)(kc0 + w_kk[i]) * 16 + w_cq[i]];
            #pragma unroll
            for (int i = 0; i < 2; ++i) {
                xreg[i] = make_uint4(0u, 0u, 0u, 0u);
                if (x_grow[i] < N)
                    xreg[i] = F16[(long long)x_grow[i] * 8 + kc0 / 8 + x_q[i]];
            }
        }

        #pragma unroll
        for (int k = 0; k < KC; ++k) {
            float4 xa = *(const float4*)&sX[k * XSTR + r * 8 + 0];
            float4 xb = *(const float4*)&sX[k * XSTR + r * 8 + 4];
            float4 w  = *(const float4*)&sW[k * 64 + c * 4];
            unsigned long long xp[4];
            xp[0] = *(unsigned long long*)&xa.x;
            xp[1] = *(unsigned long long*)&xa.z;
            xp[2] = *(unsigned long long*)&xb.x;
            xp[3] = *(unsigned long long*)&xb.z;
            float wv[4] = {w.x, w.y, w.z, w.w};
            #pragma unroll
            for (int j = 0; j < 4; ++j) {
                unsigned long long wd;
                asm("mov.b64 %0, {%1, %1};" : "=l"(wd) : "f"(wv[j]));
                #pragma unroll
                for (int rp = 0; rp < 4; ++rp) fma2(acc[rp][j], xp[rp], wd);
            }
        }
        __syncthreads();
    }

    #pragma unroll
    for (int rp = 0; rp < 4; ++rp) {
        #pragma unroll
        for (int half = 0; half < 2; ++half) {
            int row = row0 + r * 8 + rp * 2 + half;
            if (row < N) {
                float d = rsqrtf((float)(cursor[row] + 1));
                float o0 = ((float*)&acc[rp][0])[half] * d;
                float o1 = ((float*)&acc[rp][1])[half] * d;
                float o2 = ((float*)&acc[rp][2])[half] * d;
                float o3 = ((float*)&acc[rp][3])[half] * d;
                __half2 p0 = __floats2half2_rn(o0, o1);
                __half2 p1 = __floats2half2_rn(o2, o3);
                uint2 u;
                u.x = *(unsigned*)&p0;
                u.y = *(unsigned*)&p1;
                hs16[(long long)row * 16 + c] = u;
            }
        }
    }
}

// ---------------------------------------------------------------------------
// fp16 HADD2 accumulation helpers
// ---------------------------------------------------------------------------
__device__ __forceinline__ void hacc_u4(__half2* a, uint4 v) {
    a[0] = __hadd2(a[0], *(__half2*)&v.x);
    a[1] = __hadd2(a[1], *(__half2*)&v.y);
    a[2] = __hadd2(a[2], *(__half2*)&v.z);
    a[3] = __hadd2(a[3], *(__half2*)&v.w);
}

// core gather: fp16 accumulate, fp32 finalize f[8] = relu(d*agg + b)
__device__ __forceinline__ void gather_node(
    const uint4* __restrict__ hs, const int* __restrict__ cursor,
    const int* __restrict__ csr, const float* __restrict__ b,
    int node, int h, float* f, float& dout)
{
    uint4 self = hs[(long long)node * 8 + h];
    __half2 a[4];
    a[0] = *(__half2*)&self.x;
    a[1] = *(__half2*)&self.y;
    a[2] = *(__half2*)&self.z;
    a[3] = *(__half2*)&self.w;

    int deg = cursor[node];
    if (deg > CAP) deg = CAP;
    float d = rsqrtf((float)(deg + 1));
    dout = d;
    const int* nb = csr + (long long)node * CAP;

    int p = 0;
    for (; p + 7 < deg; p += 8) {
        int s[8];
        #pragma unroll
        for (int i = 0; i < 8; ++i) s[i] = nb[p + i];
        uint4 v[8];
        #pragma unroll
        for (int i = 0; i < 8; ++i) v[i] = __ldg(&hs[(long long)s[i] * 8 + h]);
        #pragma unroll
        for (int i = 0; i < 8; ++i) hacc_u4(a, v[i]);
    }
    for (; p + 3 < deg; p += 4) {
        uint4 v0 = __ldg(&hs[(long long)nb[p]     * 8 + h]);
        uint4 v1 = __ldg(&hs[(long long)nb[p + 1] * 8 + h]);
        uint4 v2 = __ldg(&hs[(long long)nb[p + 2] * 8 + h]);
        uint4 v3 = __ldg(&hs[(long long)nb[p + 3] * 8 + h]);
        hacc_u4(a, v0); hacc_u4(a, v1); hacc_u4(a, v2); hacc_u4(a, v3);
    }
    for (; p < deg; ++p) {
        uint4 v0 = __ldg(&hs[(long long)nb[p] * 8 + h]);
        hacc_u4(a, v0);
    }

    float2 s0 = __half22float2(a[0]);
    float2 s1 = __half22float2(a[1]);
    float2 s2 = __half22float2(a[2]);
    float2 s3 = __half22float2(a[3]);

    float4 b0 = ((const float4*)b)[h * 2 + 0];
    float4 b1 = ((const float4*)b)[h * 2 + 1];
    f[0] = fmaxf(fmaf(d, s0.x, b0.x), 0.f);
    f[1] = fmaxf(fmaf(d, s0.y, b0.y), 0.f);
    f[2] = fmaxf(fmaf(d, s1.x, b0.z), 0.f);
    f[3] = fmaxf(fmaf(d, s1.y, b0.w), 0.f);
    f[4] = fmaxf(fmaf(d, s2.x, b1.x), 0.f);
    f[5] = fmaxf(fmaf(d, s2.y, b1.y), 0.f);
    f[6] = fmaxf(fmaf(d, s3.x, b1.z), 0.f);
    f[7] = fmaxf(fmaf(d, s3.y, b1.w), 0.f);
}

// aggregation -> fp16 feat (uint4 per lane, coalesced)
__global__ void __launch_bounds__(256) k_agg_f16(
    const uint4* __restrict__ hs, const int* __restrict__ cursor,
    const int* __restrict__ csr, const float* __restrict__ b,
    uint4* __restrict__ feat16, int N)
{
    int node = blockIdx.x * 32 + (threadIdx.x >> 3);
    int h = threadIdx.x & 7;
    if (node >= N) return;
    float f[8], d;
    gather_node(hs, cursor, csr, b, node, h, f, d);
    __half2 p0 = __floats2half2_rn(f[0], f[1]);
    __half2 p1 = __floats2half2_rn(f[2], f[3]);
    __half2 p2 = __floats2half2_rn(f[4], f[5]);
    __half2 p3 = __floats2half2_rn(f[6], f[7]);
    uint4 u;
    u.x = *(unsigned*)&p0;
    u.y = *(unsigned*)&p1;
    u.z = *(unsigned*)&p2;
    u.w = *(unsigned*)&p3;
    feat16[(long long)node * 8 + h] = u;
}

// final aggregation + readout
__global__ void __launch_bounds__(256) k_agg_readout(
    const uint4* __restrict__ hs, const int* __restrict__ cursor,
    const int* __restrict__ csr, const float* __restrict__ b,
    float* __restrict__ out, const float* __restrict__ Wout,
    const float* __restrict__ bout, int N)
{
    int node = blockIdx.x * 32 + (threadIdx.x >> 3);
    int h = threadIdx.x & 7;
    if (node >= N) return;
    float f[8], d;
    gather_node(hs, cursor, csr, b, node, h, f, d);
    float4 w0 = ((const float4*)Wout)[h * 2 + 0];
    float4 w1 = ((const float4*)Wout)[h * 2 + 1];
    float s = f[0]*w0.x + f[1]*w0.y + f[2]*w0.z + f[3]*w0.w
            + f[4]*w1.x + f[5]*w1.y + f[6]*w1.z + f[7]*w1.w;
    #pragma unroll
    for (int o = 4; o; o >>= 1) s += __shfl_xor_sync(0xFFFFFFFFu, s, o);
    if (h == 0) out[node] = s + bout[0];
}

// ---------------------------------------------------------------------------
extern "C" void kernel_launch(void* const* d_in, const int* in_sizes, int n_in,
                              void* d_out, int out_size)
{
    const float* x    = (const float*)d_in[0];
    const void*  eraw = d_in[1];
    const float* W1   = (const float*)d_in[2];
    const float* b1   = (const float*)d_in[3];
    const float* W2   = (const float*)d_in[4];
    const float* b2   = (const float*)d_in[5];
    const float* W3   = (const float*)d_in[6];
    const float* b3   = (const float*)d_in[7];
    const float* Wout = (const float*)d_in[8];
    const float* bout = (const float*)d_in[9];
    float*       out  = (float*)d_out;

    const int N = in_sizes[0] / 128;
    const long long E = in_sizes[1] / 2;

    void *hsAv, *featBv;
    int *flag, *cursor, *csr;
    cudaGetSymbolAddress(&hsAv,            g_hsA);
    cudaGetSymbolAddress(&featBv,          g_featB);
    cudaGetSymbolAddress((void**)&flag,    g_is_i32);
    cudaGetSymbolAddress((void**)&cursor,  g_cursor);
    cudaGetSymbolAddress((void**)&csr,     g_csr);

    const int TB = 256;
    long long nwords = E < 4096 ? E : 4096;

    const int gemm_blocks  = (N + 127) / 128;
    const int agg_blocks   = (N + 31) / 32;
    const int edge4_blocks = (int)((E + 4LL * TB - 1) / (4LL * TB));

    // 0: zero cursor + dtype detect
    k_detect_zero<<<(N + TB - 1) / TB, TB>>>(
        (const unsigned long long*)eraw, nwords, (unsigned long long)N,
        flag, cursor, N);
    // 1: bucket scatter
    k_scatter<<<edge4_blocks, TB>>>(eraw, cursor, csr, E, flag);
    // 2: GEMM layer 1 -> hsA
    k_gemm1<<<gemm_blocks, 256>>>(x, W1, cursor, (uint2*)hsAv, N);
    // 3: agg1 -> featB (fp16, HADD2 accumulate)   [profiled launch]
    k_agg_f16<<<agg_blocks, TB>>>((const uint4*)hsAv, cursor, csr, b1,
                                  (uint4*)featBv, N);
    // 4: GEMM layer 2 (fp16 in) -> hsA
    k_gemm16<<<gemm_blocks, 256>>>((const uint4*)featBv, W2, cursor,
                                   (uint2*)hsAv, N);
    // 5: agg2 -> featB
    k_agg_f16<<<agg_blocks, TB>>>((const uint4*)hsAv, cursor, csr, b2,
                                  (uint4*)featBv, N);
    // 6: GEMM layer 3 (fp16 in) -> hsA
    k_gemm16<<<gemm_blocks, 256>>>((const uint4*)featBv, W3, cursor,
                                   (uint2*)hsAv, N);
    // 7: final agg + readout
    k_agg_readout<<<agg_blocks, TB>>>((const uint4*)hsAv, cursor, csr, b3,
                                      out, Wout, bout, N);
}